// round 15
// baseline (speedup 1.0000x reference)
#include <cuda_runtime.h>

// FNO with global head. B=16, C=16, H=W=256, L=4, modes 16x16.
// R15: R14 base (529us); ydft reverted to split-4/grid-512 (R13 measured best);
//      mix back to 4 partials; hsynth converted to 3xTF32 mma (grid 2048).

#define Bn 16
#define Cn 16
#define Hn 256
#define Wn 256
#define Ln 4
#define BCHW (Bn*Cn*Hn*Wn)
#define PP (Bn*Cn*1024)

__device__ float g_v0[BCHW];                 // ping
__device__ float g_v1[BCHW];                 // pong
__device__ float g_a  [Bn*Cn*Hn*32];         // x-DFT result [row][2kx+ri]
__device__ float g_a0 [Bn*Hn*32];            // layer-0 x-DFT of raw x
__device__ float g_vftp[4*PP];               // ydft partials [ks][bc][...]
__device__ float g_mix[Bn*Cn*32*32];         // after channel mix
__device__ float g_gs [Bn*Cn*Hn*32];         // h-synth [bc*256+h][kx*2+ri]
__device__ float g_ehi[256*32];              // xdft E hi (tf32-rounded)
__device__ float g_elo[256*32];              // xdft E lo (residual)
__device__ float g_xc[16*256];               // wsynth cos[kx][w]
__device__ float g_xs[16*256];               // wsynth sin[kx][w]
__device__ float g_Thi[64*512];              // ydft T hi: [2m+ri][2h+p]
__device__ float g_Tlo[64*512];              // ydft T lo (residual)
__device__ float g_E3hi[512*64];             // hsynth E3 hi: [2h+ro][2m+p]
__device__ float g_E3lo[512*64];             // hsynth E3 lo (residual)
__device__ float g_pool[Bn*256*128];         // proj partial sums (per b,h)

__device__ __forceinline__ float gelu_t(float x) {
    const float k0 = 0.7978845608028654f;
    const float k1 = 0.044715f;
    float y = k0 * x * (1.0f + k1 * x * x);
    float th;
    asm("tanh.approx.f32 %0, %1;" : "=f"(th) : "f"(y));
    return 0.5f * x * (1.0f + th);
}

__device__ __forceinline__ unsigned f2tf32(float f) {
    unsigned u;
    asm("cvt.rna.tf32.f32 %0, %1;" : "=r"(u) : "f"(f));
    return u;
}

#define MMA_TF32(D, A, B0, B1)                                            \
    asm volatile(                                                          \
        "mma.sync.aligned.m16n8k8.row.col.f32.tf32.tf32.f32 "             \
        "{%0,%1,%2,%3}, {%4,%5,%6,%7}, {%8,%9}, {%0,%1,%2,%3};\n"         \
        : "+f"(D[0]), "+f"(D[1]), "+f"(D[2]), "+f"(D[3])                   \
        : "r"(A[0]), "r"(A[1]), "r"(A[2]), "r"(A[3]), "r"(B0), "r"(B1))

// ---------------- build all constant tables (grid 576) ----------------
__global__ void k_tw() {
    int j = blockIdx.x * 256 + threadIdx.x;
    if (j < 8192) {                                   // g_ehi / g_elo
        int w = j >> 5, c = j & 31;
        int kx = c >> 1, ri = c & 1;
        float ang = (float)((kx * w) & 255) / 128.0f;
        float e = ri ? -sinpif(ang) : cospif(ang);
        float hi = __uint_as_float(f2tf32(e));
        g_ehi[j] = hi;
        g_elo[j] = __uint_as_float(f2tf32(e - hi));
    } else if (j < 12288) {                           // g_xc
        int e = j - 8192;
        int kx = e >> 8, w = e & 255;
        g_xc[e] = cospif((float)((kx * w) & 255) / 128.0f);
    } else if (j < 16384) {                           // g_xs
        int e = j - 12288;
        int kx = e >> 8, w = e & 255;
        g_xs[e] = sinpif((float)((kx * w) & 255) / 128.0f);
    } else if (j < 49152) {                           // g_Thi [2m+ri][2h+p]
        int e = j - 16384;
        int row = e >> 9, col = e & 511;
        int m = row >> 1, ri = row & 1;
        int h = col >> 1, p = col & 1;
        int ky = (m < 16) ? m : (m + 224);
        float ang = (float)((ky * h) & 255) / 128.0f;
        float cy = cospif(ang), sy = sinpif(ang);
        float v = (ri == 0) ? (p == 0 ? cy : sy) : (p == 0 ? -sy : cy);
        g_Thi[e] = __uint_as_float(f2tf32(v));
    } else if (j < 81920) {                           // g_E3hi [2h+ro][2m+p]
        int e = j - 49152;
        int row = e >> 6, col = e & 63;
        int h = row >> 1, ro = row & 1;
        int m = col >> 1, p = col & 1;
        int ky = (m < 16) ? m : (m + 224);
        float ang = (float)((ky * h) & 255) / 128.0f;
        float cy = cospif(ang), sy = sinpif(ang);
        float v = (ro == 0) ? (p == 0 ? cy : -sy) : (p == 0 ? sy : cy);
        g_E3hi[e] = __uint_as_float(f2tf32(v));
    } else if (j < 114688) {                          // g_Tlo
        int e = j - 81920;
        int row = e >> 9, col = e & 511;
        int m = row >> 1, ri = row & 1;
        int h = col >> 1, p = col & 1;
        int ky = (m < 16) ? m : (m + 224);
        float ang = (float)((ky * h) & 255) / 128.0f;
        float cy = cospif(ang), sy = sinpif(ang);
        float v = (ri == 0) ? (p == 0 ? cy : sy) : (p == 0 ? -sy : cy);
        float hi = __uint_as_float(f2tf32(v));
        g_Tlo[e] = __uint_as_float(f2tf32(v - hi));
    } else if (j < 147456) {                          // g_E3lo
        int e = j - 114688;
        int row = e >> 6, col = e & 63;
        int h = row >> 1, ro = row & 1;
        int m = col >> 1, p = col & 1;
        int ky = (m < 16) ? m : (m + 224);
        float ang = (float)((ky * h) & 255) / 128.0f;
        float cy = cospif(ang), sy = sinpif(ang);
        float v = (ro == 0) ? (p == 0 ? cy : -sy) : (p == 0 ? sy : cy);
        float hi = __uint_as_float(f2tf32(v));
        g_E3lo[e] = __uint_as_float(f2tf32(v - hi));
    }
}

// ---------------- generic x-DFT body (3xTF32), src rows -> dst -----------
__device__ __forceinline__ void xdft_body(const float* __restrict__ src,
                                          float* __restrict__ dst,
                                          int rowbase) {
    __shared__ float vs[64][68];
    __shared__ float eh[64][40];
    __shared__ float el[64][40];
    int t = threadIdx.x;
    int lane = t & 31, warp = t >> 5;
    int gid = lane >> 2, tig = lane & 3;
    const float* s = src + (size_t)rowbase * 256;
    float d[4][4] = {};
    for (int kc = 0; kc < 4; kc++) {
        __syncthreads();
        for (int j = t; j < 1024; j += 128) {
            int r = j >> 4, q = j & 15;
            float4 v4 = *(const float4*)(s + r * 256 + kc * 64 + q * 4);
            vs[r][q * 4 + 0] = v4.x; vs[r][q * 4 + 1] = v4.y;
            vs[r][q * 4 + 2] = v4.z; vs[r][q * 4 + 3] = v4.w;
        }
        for (int j = t; j < 512; j += 128) {
            int k = j >> 3, q = j & 7;
            float4 h4 = *(const float4*)(g_ehi + (size_t)(kc * 64 + k) * 32 + q * 4);
            eh[k][q * 4 + 0] = h4.x; eh[k][q * 4 + 1] = h4.y;
            eh[k][q * 4 + 2] = h4.z; eh[k][q * 4 + 3] = h4.w;
            float4 l4 = *(const float4*)(g_elo + (size_t)(kc * 64 + k) * 32 + q * 4);
            el[k][q * 4 + 0] = l4.x; el[k][q * 4 + 1] = l4.y;
            el[k][q * 4 + 2] = l4.z; el[k][q * 4 + 3] = l4.w;
        }
        __syncthreads();
        #pragma unroll
        for (int ks = 0; ks < 8; ks++) {
            int kk = ks * 8;
            int m0 = warp * 16 + gid;
            float va[4];
            va[0] = vs[m0][kk + tig];     va[1] = vs[m0 + 8][kk + tig];
            va[2] = vs[m0][kk + tig + 4]; va[3] = vs[m0 + 8][kk + tig + 4];
            unsigned ah[4], al_[4];
            #pragma unroll
            for (int i = 0; i < 4; i++) {
                ah[i] = f2tf32(va[i]);
                al_[i] = f2tf32(va[i] - __uint_as_float(ah[i]));
            }
            #pragma unroll
            for (int nt = 0; nt < 4; nt++) {
                int n = nt * 8 + gid;
                unsigned bh0 = __float_as_uint(eh[kk + tig][n]);
                unsigned bh1 = __float_as_uint(eh[kk + tig + 4][n]);
                unsigned bl0 = __float_as_uint(el[kk + tig][n]);
                unsigned bl1 = __float_as_uint(el[kk + tig + 4][n]);
                MMA_TF32(d[nt], ah, bh0, bh1);
                MMA_TF32(d[nt], al_, bh0, bh1);
                MMA_TF32(d[nt], ah, bl0, bl1);
            }
        }
    }
    int m0 = rowbase + warp * 16 + gid;
    #pragma unroll
    for (int nt = 0; nt < 4; nt++) {
        int c0 = nt * 8 + 2 * tig;
        *(float2*)(dst + (size_t)m0 * 32 + c0) = make_float2(d[nt][0], d[nt][1]);
        *(float2*)(dst + (size_t)(m0 + 8) * 32 + c0) = make_float2(d[nt][2], d[nt][3]);
    }
}

__global__ void __launch_bounds__(128) k_xdft(int flip) {
    xdft_body(flip ? g_v1 : g_v0, g_a, blockIdx.x * 64);
}

// layer-0: DFT of raw x, 4096 rows (grid 64)
__global__ void __launch_bounds__(128) k_xdft0(const float* __restrict__ x) {
    xdft_body(x, g_a0, blockIdx.x * 64);
}

// expand: g_a[b,c,h,:] = lw[c]*g_a0[b,h,:] + 256*lb[c]*delta(idx==0)
__global__ void __launch_bounds__(256) k_expand(const float* __restrict__ lw,
                                                const float* __restrict__ lb) {
    int j = blockIdx.x * 256 + threadIdx.x;   // 524288 float4 groups
    int c2 = (j * 4) & 31;
    int h = (j >> 3) & 255;
    int c = (j >> 11) & 15;
    int b = j >> 15;
    float4 v = *(const float4*)(g_a0 + (size_t)((b * 256 + h) * 32) + c2);
    float s = lw[c];
    v.x *= s; v.y *= s; v.z *= s; v.w *= s;
    if (c2 == 0) v.x += 256.0f * lb[c];
    *(float4*)(g_a + (size_t)(((b * 16 + c) * 256 + h) * 32) + c2) = v;
}

// ---------------- y-DFT via 3xTF32 mma, K-split x4 (R13 form) -------------
// grid 512 = (bc/2)*4; block: C_part[64,32] over two 64-k chunks.
__global__ void __launch_bounds__(128) k_ydft() {
    __shared__ float th[64][68];      // Thi chunk [row][k]
    __shared__ float tl[64][68];      // Tlo chunk
    __shared__ float as[64][36];      // A chunk [k][col=bcq*16+kx]
    int t = threadIdx.x;
    int lane = t & 31, warp = t >> 5;
    int gid = lane >> 2, tig = lane & 3;
    int ks4 = blockIdx.x & 3;
    int bc0 = (blockIdx.x >> 2) * 2;
    float d[4][4] = {};
    for (int ci = 0; ci < 2; ci++) {
        int ch = ks4 * 2 + ci;
        int h0 = ch * 32, k0 = ch * 64;
        __syncthreads();
        for (int j = t; j < 1024; j += 128) {
            int row = j >> 4, q = j & 15;
            float4 h4 = *(const float4*)(g_Thi + (size_t)row * 512 + k0 + q * 4);
            th[row][q * 4 + 0] = h4.x; th[row][q * 4 + 1] = h4.y;
            th[row][q * 4 + 2] = h4.z; th[row][q * 4 + 3] = h4.w;
            float4 l4 = *(const float4*)(g_Tlo + (size_t)row * 512 + k0 + q * 4);
            tl[row][q * 4 + 0] = l4.x; tl[row][q * 4 + 1] = l4.y;
            tl[row][q * 4 + 2] = l4.z; tl[row][q * 4 + 3] = l4.w;
        }
        for (int j = t; j < 512; j += 128) {
            int bcq = j >> 8, rem = j & 255, hh = rem >> 3, q = rem & 7;
            float4 v4 = *(const float4*)(g_a + (size_t)((bc0 + bcq) * 256 + h0 + hh) * 32 + q * 4);
            int n0 = bcq * 16 + q * 2;
            as[2 * hh + 0][n0] = v4.x;     as[2 * hh + 1][n0] = v4.y;
            as[2 * hh + 0][n0 + 1] = v4.z; as[2 * hh + 1][n0 + 1] = v4.w;
        }
        __syncthreads();
        #pragma unroll
        for (int ks = 0; ks < 8; ks++) {
            int kk = ks * 8;
            int m0 = warp * 16 + gid;
            unsigned ah[4], al_[4];
            ah[0] = __float_as_uint(th[m0][kk + tig]);
            ah[1] = __float_as_uint(th[m0 + 8][kk + tig]);
            ah[2] = __float_as_uint(th[m0][kk + tig + 4]);
            ah[3] = __float_as_uint(th[m0 + 8][kk + tig + 4]);
            al_[0] = __float_as_uint(tl[m0][kk + tig]);
            al_[1] = __float_as_uint(tl[m0 + 8][kk + tig]);
            al_[2] = __float_as_uint(tl[m0][kk + tig + 4]);
            al_[3] = __float_as_uint(tl[m0 + 8][kk + tig + 4]);
            #pragma unroll
            for (int nt = 0; nt < 4; nt++) {
                int n = nt * 8 + gid;
                float b0 = as[kk + tig][n];
                float b1 = as[kk + tig + 4][n];
                unsigned bh0 = f2tf32(b0);
                unsigned bh1 = f2tf32(b1);
                unsigned bl0 = f2tf32(b0 - __uint_as_float(bh0));
                unsigned bl1 = f2tf32(b1 - __uint_as_float(bh1));
                MMA_TF32(d[nt], ah, bh0, bh1);
                MMA_TF32(d[nt], al_, bh0, bh1);
                MMA_TF32(d[nt], ah, bl0, bl1);
            }
        }
    }
    float* vout = g_vftp + (size_t)ks4 * PP;
    #pragma unroll
    for (int nt = 0; nt < 4; nt++) {
        #pragma unroll
        for (int e = 0; e < 4; e++) {
            int r = warp * 16 + gid + (e >= 2 ? 8 : 0);
            int c = nt * 8 + 2 * tig + (e & 1);
            int m = r >> 1, ri = r & 1;
            int bcq = c >> 4, kx = c & 15;
            vout[(bc0 + bcq) * 1024 + m * 32 + kx * 2 + ri] = d[nt][e];
        }
    }
}

// ---------------- per-mode 16x16 complex channel mixing (sums 4 partials)
__global__ void k_mix(const float* __restrict__ w1r, const float* __restrict__ w1i,
                      const float* __restrict__ w2r, const float* __restrict__ w2i,
                      int l) {
    int tid = blockIdx.x * blockDim.x + threadIdx.x;   // 131072
    int kx = tid & 15;
    int m = (tid >> 4) & 31;
    int o = (tid >> 9) & 15;
    int b = tid >> 13;
    int mm = m & 15;
    const float* wr = (m < 16) ? w1r : w2r;
    const float* wi = (m < 16) ? w1i : w2i;
    float accr = 0.f, acci = 0.f;
    #pragma unroll
    for (int i = 0; i < 16; i++) {
        int vidx = (b * 16 + i) * 1024 + m * 32 + kx * 2;
        float2 p0 = *(const float2*)(g_vftp + vidx);
        float2 p1 = *(const float2*)(g_vftp + PP + vidx);
        float2 p2 = *(const float2*)(g_vftp + 2 * PP + vidx);
        float2 p3 = *(const float2*)(g_vftp + 3 * PP + vidx);
        float vr = (p0.x + p1.x) + (p2.x + p3.x);
        float vv = (p0.y + p1.y) + (p2.y + p3.y);
        int widx = (((l * 16 + i) * 16 + o) * 256) + mm * 16 + kx;
        float wrv = wr[widx], wiv = wi[widx];
        accr += vr * wrv - vv * wiv;
        acci += vr * wiv + vv * wrv;
    }
    int outi = (b * 16 + o) * 1024 + m * 32 + kx * 2;
    g_mix[outi + 0] = accr;
    g_mix[outi + 1] = acci;
}

// ---------------- h-synthesis via 3xTF32 mma -------------------------------
// grid 2048 = bc*8 + rowgroup; block = 64 output rows; 128 thr = 4 warps,
// warp = one 16-row m-tile, 2 n-tiles, 8 k-slices. A = E3 hi/lo from global
// tables (L2-resident); B = mix tile staged in smem, split on the fly.
__global__ void __launch_bounds__(128) k_hsynth() {
    __shared__ float msm[64][24];     // M[2m+p][kx]; pad 24 -> conflict-free
    int t = threadIdx.x;
    int lane = t & 31, warp = t >> 5;
    int gid = lane >> 2, tig = lane & 3;
    int bc = blockIdx.x >> 3, rg = blockIdx.x & 7;
    for (int j = t; j < 1024; j += 128) {
        int m = j >> 5, kx = (j >> 1) & 15, p = j & 1;
        msm[2 * m + p][kx] = g_mix[(size_t)bc * 1024 + j];
    }
    __syncthreads();
    int rb = rg * 64 + warp * 16;
    float d[2][4] = {};
    #pragma unroll
    for (int ks = 0; ks < 8; ks++) {
        int kk = ks * 8;
        const float* e3h = g_E3hi + (size_t)(rb + gid) * 64 + kk + tig;
        const float* e3l = g_E3lo + (size_t)(rb + gid) * 64 + kk + tig;
        unsigned ah[4], al_[4];
        ah[0] = __float_as_uint(e3h[0]);
        ah[1] = __float_as_uint(e3h[8 * 64]);
        ah[2] = __float_as_uint(e3h[4]);
        ah[3] = __float_as_uint(e3h[8 * 64 + 4]);
        al_[0] = __float_as_uint(e3l[0]);
        al_[1] = __float_as_uint(e3l[8 * 64]);
        al_[2] = __float_as_uint(e3l[4]);
        al_[3] = __float_as_uint(e3l[8 * 64 + 4]);
        #pragma unroll
        for (int nt = 0; nt < 2; nt++) {
            int n = nt * 8 + gid;
            float b0 = msm[kk + tig][n];
            float b1 = msm[kk + tig + 4][n];
            unsigned bh0 = f2tf32(b0), bh1 = f2tf32(b1);
            unsigned bl0 = f2tf32(b0 - __uint_as_float(bh0));
            unsigned bl1 = f2tf32(b1 - __uint_as_float(bh1));
            MMA_TF32(d[nt], ah, bh0, bh1);
            MMA_TF32(d[nt], al_, bh0, bh1);
            MMA_TF32(d[nt], ah, bl0, bl1);
        }
    }
    #pragma unroll
    for (int nt = 0; nt < 2; nt++) {
        #pragma unroll
        for (int e = 0; e < 4; e++) {
            int r = rb + gid + (e >= 2 ? 8 : 0);
            int kx = nt * 8 + 2 * tig + (e & 1);
            int h = r >> 1, ro = r & 1;
            float sc = (kx == 0) ? (1.0f / 65536.0f) : (2.0f / 65536.0f);
            g_gs[(size_t)(bc * 256 + h) * 32 + kx * 2 + ro] = d[nt][e] * sc;
        }
    }
}

// ---------------- fused w-synth + skip (+ gelu | + proj1+gelu+pool) ------
__global__ void __launch_bounds__(256) k_wsynth(const float* __restrict__ skw,
                         const float* __restrict__ skb,
                         const float* __restrict__ pw1,
                         const float* __restrict__ pb1,
                         const float* __restrict__ x,
                         const float* __restrict__ lw,
                         const float* __restrict__ lb,
                         int l, int mode, int first, int flip) {
    __shared__ float vs[16][260];
    __shared__ float ms[16][52];      // [o][0:16 skw | 16:32 gr | 32:48 -gi]
    __shared__ float sb[16];
    __shared__ float outs[16][264];   // staged OUT for fused proj (mode 0)
    const float* __restrict__ vin = flip ? g_v1 : g_v0;
    float* __restrict__ vout = flip ? g_v0 : g_v1;
    int t = threadIdx.x;
    int lane = t & 31, warp = t >> 5;
    int b = blockIdx.x >> 8, h = blockIdx.x & 255;
    if (first) {
        const float* xrow = x + ((size_t)b * 256 + h) * 256;
        for (int j = t; j < 1024; j += 256) {
            int c = j >> 6, q = j & 63;
            float4 v4 = *(const float4*)(xrow + q * 4);
            float s = lw[c], o = lb[c];
            vs[c][q * 4 + 0] = s * v4.x + o; vs[c][q * 4 + 1] = s * v4.y + o;
            vs[c][q * 4 + 2] = s * v4.z + o; vs[c][q * 4 + 3] = s * v4.w + o;
        }
    } else {
        for (int j = t; j < 1024; j += 256) {
            int c = j >> 6, q = j & 63;
            float4 v4 = *(const float4*)(vin + ((size_t)(b * 16 + c) * 256 + h) * 256 + q * 4);
            vs[c][q * 4 + 0] = v4.x; vs[c][q * 4 + 1] = v4.y;
            vs[c][q * 4 + 2] = v4.z; vs[c][q * 4 + 3] = v4.w;
        }
    }
    {
        int c = t >> 4, k = t & 15;
        ms[c][k] = skw[l * 256 + c * 16 + k];
        int base = ((size_t)(b * 16 + c) * 256 + h) * 32 + k * 2;
        ms[c][16 + k] = g_gs[base];
        ms[c][32 + k] = -g_gs[base + 1];
        if (t < 16) sb[t] = skb[l * 16 + t];
    }
    __syncthreads();
    int gid = lane >> 2, tig = lane & 3;
    unsigned a[6][4];
    #pragma unroll
    for (int ks = 0; ks < 6; ks++) {
        int c0 = ks * 8 + tig;
        a[ks][0] = f2tf32(ms[gid][c0]);
        a[ks][1] = f2tf32(ms[gid + 8][c0]);
        a[ks][2] = f2tf32(ms[gid][c0 + 4]);
        a[ks][3] = f2tf32(ms[gid + 8][c0 + 4]);
    }
    float bias0 = sb[gid], bias1 = sb[gid + 8];
    float* out0 = vout + ((size_t)(b * 16 + gid) * 256 + h) * 256;
    float* out1 = vout + ((size_t)(b * 16 + gid + 8) * 256 + h) * 256;
    #pragma unroll
    for (int nt = 0; nt < 4; nt++) {
        int n = warp * 32 + nt * 8 + gid;
        unsigned bf[6][2];
        bf[0][0] = f2tf32(vs[tig][n]);        bf[0][1] = f2tf32(vs[tig + 4][n]);
        bf[1][0] = f2tf32(vs[8 + tig][n]);    bf[1][1] = f2tf32(vs[12 + tig][n]);
        bf[2][0] = f2tf32(g_xc[tig * 256 + n]);
        bf[2][1] = f2tf32(g_xc[(tig + 4) * 256 + n]);
        bf[3][0] = f2tf32(g_xc[(8 + tig) * 256 + n]);
        bf[3][1] = f2tf32(g_xc[(12 + tig) * 256 + n]);
        bf[4][0] = f2tf32(g_xs[tig * 256 + n]);
        bf[4][1] = f2tf32(g_xs[(tig + 4) * 256 + n]);
        bf[5][0] = f2tf32(g_xs[(8 + tig) * 256 + n]);
        bf[5][1] = f2tf32(g_xs[(12 + tig) * 256 + n]);
        float d0 = 0.f, d1 = 0.f, d2 = 0.f, d3 = 0.f;
        #pragma unroll
        for (int ks = 0; ks < 6; ks++) {
            asm volatile(
                "mma.sync.aligned.m16n8k8.row.col.f32.tf32.tf32.f32 "
                "{%0,%1,%2,%3}, {%4,%5,%6,%7}, {%8,%9}, {%0,%1,%2,%3};\n"
                : "+f"(d0), "+f"(d1), "+f"(d2), "+f"(d3)
                : "r"(a[ks][0]), "r"(a[ks][1]), "r"(a[ks][2]), "r"(a[ks][3]),
                  "r"(bf[ks][0]), "r"(bf[ks][1]));
        }
        d0 += bias0; d1 += bias0; d2 += bias1; d3 += bias1;
        int w = warp * 32 + nt * 8 + 2 * tig;
        if (mode) {
            d0 = gelu_t(d0); d1 = gelu_t(d1);
            d2 = gelu_t(d2); d3 = gelu_t(d3);
            *(float2*)(out0 + w) = make_float2(d0, d1);
            *(float2*)(out1 + w) = make_float2(d2, d3);
        } else {
            outs[gid][w] = d0;     outs[gid][w + 1] = d1;
            outs[gid + 8][w] = d2; outs[gid + 8][w + 1] = d3;
        }
    }
    if (mode) return;
    // ---- fused proj1 + gelu + pool (mode 0) ----
    __syncthreads();
    int m_base = warp * 16;
    unsigned pa[2][4];
    float pb[2];
    {
        int r_lo = m_base + gid;
        pb[0] = pb1[r_lo];
        pb[1] = pb1[r_lo + 8];
        #pragma unroll
        for (int ks = 0; ks < 2; ks++) {
            int c_lo = ks * 8 + tig;
            pa[ks][0] = f2tf32(pw1[r_lo * 16 + c_lo]);
            pa[ks][1] = f2tf32(pw1[(r_lo + 8) * 16 + c_lo]);
            pa[ks][2] = f2tf32(pw1[r_lo * 16 + c_lo + 4]);
            pa[ks][3] = f2tf32(pw1[(r_lo + 8) * 16 + c_lo + 4]);
        }
    }
    float s0 = 0.f, s1 = 0.f;
    #pragma unroll
    for (int nt = 0; nt < 32; nt++) {
        int n = nt * 8 + gid;
        unsigned bfr[2][2];
        bfr[0][0] = f2tf32(outs[tig][n]);
        bfr[0][1] = f2tf32(outs[tig + 4][n]);
        bfr[1][0] = f2tf32(outs[8 + tig][n]);
        bfr[1][1] = f2tf32(outs[12 + tig][n]);
        float d0 = 0.f, d1 = 0.f, d2 = 0.f, d3 = 0.f;
        #pragma unroll
        for (int ks = 0; ks < 2; ks++) {
            asm volatile(
                "mma.sync.aligned.m16n8k8.row.col.f32.tf32.tf32.f32 "
                "{%0,%1,%2,%3}, {%4,%5,%6,%7}, {%8,%9}, {%0,%1,%2,%3};\n"
                : "+f"(d0), "+f"(d1), "+f"(d2), "+f"(d3)
                : "r"(pa[ks][0]), "r"(pa[ks][1]), "r"(pa[ks][2]), "r"(pa[ks][3]),
                  "r"(bfr[ks][0]), "r"(bfr[ks][1]));
        }
        s0 += gelu_t(d0 + pb[0]) + gelu_t(d1 + pb[0]);
        s1 += gelu_t(d2 + pb[1]) + gelu_t(d3 + pb[1]);
    }
    s0 += __shfl_xor_sync(0xFFFFFFFFu, s0, 1);
    s0 += __shfl_xor_sync(0xFFFFFFFFu, s0, 2);
    s1 += __shfl_xor_sync(0xFFFFFFFFu, s1, 1);
    s1 += __shfl_xor_sync(0xFFFFFFFFu, s1, 2);
    if (tig == 0) {
        float* dst = g_pool + (size_t)(b * 256 + h) * 128;
        dst[m_base + gid] = s0;
        dst[m_base + gid + 8] = s1;
    }
}

// ---------------- final reduce + proj2 on pooled vector + head -----------
__global__ void k_head(const float* __restrict__ w2, const float* __restrict__ b2,
                       const float* __restrict__ hw_, const float* __restrict__ hb,
                       float* __restrict__ out) {
    __shared__ float pq[128];
    __shared__ float f[64];
    int b = blockIdx.x, t = threadIdx.x;
    float s = 0.f;
    for (int k = 0; k < 256; k++)
        s += g_pool[((size_t)(b * 256 + k)) * 128 + t];
    pq[t] = s * (1.0f / 65536.0f);
    __syncthreads();
    if (t < 64) {
        float a = b2[t];
        #pragma unroll 8
        for (int i = 0; i < 128; i++) a += w2[t * 128 + i] * pq[i];
        f[t] = a;
    }
    __syncthreads();
    if (t < 2) {
        float a = hb[t];
        #pragma unroll
        for (int o = 0; o < 64; o++) a += hw_[t * 64 + o] * f[o];
        float e = __expf(2.0f * a);
        out[b * 2 + t] = 1.0f - 2.0f / (e + 1.0f);
    }
}

extern "C" void kernel_launch(void* const* d_in, const int* in_sizes, int n_in,
                              void* d_out, int out_size) {
    const float* x    = (const float*)d_in[0];
    const float* lw   = (const float*)d_in[1];
    const float* lb   = (const float*)d_in[2];
    const float* w1r  = (const float*)d_in[3];
    const float* w1i  = (const float*)d_in[4];
    const float* w2r  = (const float*)d_in[5];
    const float* w2i  = (const float*)d_in[6];
    const float* skw  = (const float*)d_in[7];
    const float* skb  = (const float*)d_in[8];
    const float* pw1  = (const float*)d_in[9];
    const float* pb1  = (const float*)d_in[10];
    const float* pw2  = (const float*)d_in[11];
    const float* pb2  = (const float*)d_in[12];
    const float* hw_  = (const float*)d_in[13];
    const float* hb   = (const float*)d_in[14];
    float* out = (float*)d_out;

    k_tw<<<576, 256>>>();
    for (int l = 0; l < Ln; l++) {
        int flip = l & 1;
        if (l == 0) {
            k_xdft0 <<<64, 128>>>(x);
            k_expand<<<2048, 256>>>(lw, lb);
        } else {
            k_xdft  <<<1024, 128>>>(flip);
        }
        k_ydft  <<<512, 128>>>();
        k_mix   <<<512, 256>>>(w1r, w1i, w2r, w2i, l);
        k_hsynth<<<2048, 128>>>();
        k_wsynth<<<4096, 256>>>(skw, skb, pw1, pb1, x, lw, lb, l,
                                (l < Ln - 1) ? 1 : 0, (l == 0) ? 1 : 0, flip);
    }
    k_head<<<Bn, 128>>>(pw2, pb2, hw_, hb, out);
}

// round 16
// speedup vs baseline: 1.0761x; 1.0761x over previous
#include <cuda_runtime.h>

// FNO with global head. B=16, C=16, H=W=256, L=4, modes 16x16.
// R16: recomposition of measured-best parts: R15 with hsynth reverted to
//      scalar (grid 256) — ydft split-4, mix-4, lift-eliminated, fused tail.

#define Bn 16
#define Cn 16
#define Hn 256
#define Wn 256
#define Ln 4
#define BCHW (Bn*Cn*Hn*Wn)
#define PP (Bn*Cn*1024)

__device__ float g_v0[BCHW];                 // ping
__device__ float g_v1[BCHW];                 // pong
__device__ float g_a  [Bn*Cn*Hn*32];         // x-DFT result [row][2kx+ri]
__device__ float g_a0 [Bn*Hn*32];            // layer-0 x-DFT of raw x
__device__ float g_vftp[4*PP];               // ydft partials [ks][bc][...]
__device__ float g_mix[Bn*Cn*32*32];         // after channel mix
__device__ float g_gs [Bn*Cn*Hn*32];         // h-synth [bc*256+h][kx*2+ri]
__device__ float g_ehi[256*32];              // xdft E hi (tf32-rounded)
__device__ float g_elo[256*32];              // xdft E lo (residual)
__device__ float g_xc[16*256];               // wsynth cos[kx][w]
__device__ float g_xs[16*256];               // wsynth sin[kx][w]
__device__ float g_Thi[64*512];              // ydft T hi: [2m+ri][2h+p]
__device__ float g_Tlo[64*512];              // ydft T lo (residual)
__device__ float g_E3[512*64];               // hsynth E3 (fp32): [2h+ro][2m+p]
__device__ float g_pool[Bn*256*128];         // proj partial sums (per b,h)

__device__ __forceinline__ float gelu_t(float x) {
    const float k0 = 0.7978845608028654f;
    const float k1 = 0.044715f;
    float y = k0 * x * (1.0f + k1 * x * x);
    float th;
    asm("tanh.approx.f32 %0, %1;" : "=f"(th) : "f"(y));
    return 0.5f * x * (1.0f + th);
}

__device__ __forceinline__ unsigned f2tf32(float f) {
    unsigned u;
    asm("cvt.rna.tf32.f32 %0, %1;" : "=r"(u) : "f"(f));
    return u;
}

#define MMA_TF32(D, A, B0, B1)                                            \
    asm volatile(                                                          \
        "mma.sync.aligned.m16n8k8.row.col.f32.tf32.tf32.f32 "             \
        "{%0,%1,%2,%3}, {%4,%5,%6,%7}, {%8,%9}, {%0,%1,%2,%3};\n"         \
        : "+f"(D[0]), "+f"(D[1]), "+f"(D[2]), "+f"(D[3])                   \
        : "r"(A[0]), "r"(A[1]), "r"(A[2]), "r"(A[3]), "r"(B0), "r"(B1))

// ---------------- build all constant tables (grid 448) ----------------
__global__ void k_tw() {
    int j = blockIdx.x * 256 + threadIdx.x;
    if (j < 8192) {                                   // g_ehi / g_elo
        int w = j >> 5, c = j & 31;
        int kx = c >> 1, ri = c & 1;
        float ang = (float)((kx * w) & 255) / 128.0f;
        float e = ri ? -sinpif(ang) : cospif(ang);
        float hi = __uint_as_float(f2tf32(e));
        g_ehi[j] = hi;
        g_elo[j] = __uint_as_float(f2tf32(e - hi));
    } else if (j < 12288) {                           // g_xc
        int e = j - 8192;
        int kx = e >> 8, w = e & 255;
        g_xc[e] = cospif((float)((kx * w) & 255) / 128.0f);
    } else if (j < 16384) {                           // g_xs
        int e = j - 12288;
        int kx = e >> 8, w = e & 255;
        g_xs[e] = sinpif((float)((kx * w) & 255) / 128.0f);
    } else if (j < 49152) {                           // g_Thi [2m+ri][2h+p]
        int e = j - 16384;
        int row = e >> 9, col = e & 511;
        int m = row >> 1, ri = row & 1;
        int h = col >> 1, p = col & 1;
        int ky = (m < 16) ? m : (m + 224);
        float ang = (float)((ky * h) & 255) / 128.0f;
        float cy = cospif(ang), sy = sinpif(ang);
        float v = (ri == 0) ? (p == 0 ? cy : sy) : (p == 0 ? -sy : cy);
        g_Thi[e] = __uint_as_float(f2tf32(v));
    } else if (j < 81920) {                           // g_E3 fp32 [2h+ro][2m+p]
        int e = j - 49152;
        int row = e >> 6, col = e & 63;
        int h = row >> 1, ro = row & 1;
        int m = col >> 1, p = col & 1;
        int ky = (m < 16) ? m : (m + 224);
        float ang = (float)((ky * h) & 255) / 128.0f;
        float cy = cospif(ang), sy = sinpif(ang);
        g_E3[e] = (ro == 0) ? (p == 0 ? cy : -sy) : (p == 0 ? sy : cy);
    } else if (j < 114688) {                          // g_Tlo
        int e = j - 81920;
        int row = e >> 9, col = e & 511;
        int m = row >> 1, ri = row & 1;
        int h = col >> 1, p = col & 1;
        int ky = (m < 16) ? m : (m + 224);
        float ang = (float)((ky * h) & 255) / 128.0f;
        float cy = cospif(ang), sy = sinpif(ang);
        float v = (ri == 0) ? (p == 0 ? cy : sy) : (p == 0 ? -sy : cy);
        float hi = __uint_as_float(f2tf32(v));
        g_Tlo[e] = __uint_as_float(f2tf32(v - hi));
    }
}

// ---------------- generic x-DFT body (3xTF32), src rows -> dst -----------
__device__ __forceinline__ void xdft_body(const float* __restrict__ src,
                                          float* __restrict__ dst,
                                          int rowbase) {
    __shared__ float vs[64][68];
    __shared__ float eh[64][40];
    __shared__ float el[64][40];
    int t = threadIdx.x;
    int lane = t & 31, warp = t >> 5;
    int gid = lane >> 2, tig = lane & 3;
    const float* s = src + (size_t)rowbase * 256;
    float d[4][4] = {};
    for (int kc = 0; kc < 4; kc++) {
        __syncthreads();
        for (int j = t; j < 1024; j += 128) {
            int r = j >> 4, q = j & 15;
            float4 v4 = *(const float4*)(s + r * 256 + kc * 64 + q * 4);
            vs[r][q * 4 + 0] = v4.x; vs[r][q * 4 + 1] = v4.y;
            vs[r][q * 4 + 2] = v4.z; vs[r][q * 4 + 3] = v4.w;
        }
        for (int j = t; j < 512; j += 128) {
            int k = j >> 3, q = j & 7;
            float4 h4 = *(const float4*)(g_ehi + (size_t)(kc * 64 + k) * 32 + q * 4);
            eh[k][q * 4 + 0] = h4.x; eh[k][q * 4 + 1] = h4.y;
            eh[k][q * 4 + 2] = h4.z; eh[k][q * 4 + 3] = h4.w;
            float4 l4 = *(const float4*)(g_elo + (size_t)(kc * 64 + k) * 32 + q * 4);
            el[k][q * 4 + 0] = l4.x; el[k][q * 4 + 1] = l4.y;
            el[k][q * 4 + 2] = l4.z; el[k][q * 4 + 3] = l4.w;
        }
        __syncthreads();
        #pragma unroll
        for (int ks = 0; ks < 8; ks++) {
            int kk = ks * 8;
            int m0 = warp * 16 + gid;
            float va[4];
            va[0] = vs[m0][kk + tig];     va[1] = vs[m0 + 8][kk + tig];
            va[2] = vs[m0][kk + tig + 4]; va[3] = vs[m0 + 8][kk + tig + 4];
            unsigned ah[4], al_[4];
            #pragma unroll
            for (int i = 0; i < 4; i++) {
                ah[i] = f2tf32(va[i]);
                al_[i] = f2tf32(va[i] - __uint_as_float(ah[i]));
            }
            #pragma unroll
            for (int nt = 0; nt < 4; nt++) {
                int n = nt * 8 + gid;
                unsigned bh0 = __float_as_uint(eh[kk + tig][n]);
                unsigned bh1 = __float_as_uint(eh[kk + tig + 4][n]);
                unsigned bl0 = __float_as_uint(el[kk + tig][n]);
                unsigned bl1 = __float_as_uint(el[kk + tig + 4][n]);
                MMA_TF32(d[nt], ah, bh0, bh1);
                MMA_TF32(d[nt], al_, bh0, bh1);
                MMA_TF32(d[nt], ah, bl0, bl1);
            }
        }
    }
    int m0 = rowbase + warp * 16 + gid;
    #pragma unroll
    for (int nt = 0; nt < 4; nt++) {
        int c0 = nt * 8 + 2 * tig;
        *(float2*)(dst + (size_t)m0 * 32 + c0) = make_float2(d[nt][0], d[nt][1]);
        *(float2*)(dst + (size_t)(m0 + 8) * 32 + c0) = make_float2(d[nt][2], d[nt][3]);
    }
}

__global__ void __launch_bounds__(128) k_xdft(int flip) {
    xdft_body(flip ? g_v1 : g_v0, g_a, blockIdx.x * 64);
}

// layer-0: DFT of raw x, 4096 rows (grid 64)
__global__ void __launch_bounds__(128) k_xdft0(const float* __restrict__ x) {
    xdft_body(x, g_a0, blockIdx.x * 64);
}

// expand: g_a[b,c,h,:] = lw[c]*g_a0[b,h,:] + 256*lb[c]*delta(idx==0)
__global__ void __launch_bounds__(256) k_expand(const float* __restrict__ lw,
                                                const float* __restrict__ lb) {
    int j = blockIdx.x * 256 + threadIdx.x;   // 524288 float4 groups
    int c2 = (j * 4) & 31;
    int h = (j >> 3) & 255;
    int c = (j >> 11) & 15;
    int b = j >> 15;
    float4 v = *(const float4*)(g_a0 + (size_t)((b * 256 + h) * 32) + c2);
    float s = lw[c];
    v.x *= s; v.y *= s; v.z *= s; v.w *= s;
    if (c2 == 0) v.x += 256.0f * lb[c];
    *(float4*)(g_a + (size_t)(((b * 16 + c) * 256 + h) * 32) + c2) = v;
}

// ---------------- y-DFT via 3xTF32 mma, K-split x4 (R13 form) -------------
__global__ void __launch_bounds__(128) k_ydft() {
    __shared__ float th[64][68];      // Thi chunk [row][k]
    __shared__ float tl[64][68];      // Tlo chunk
    __shared__ float as[64][36];      // A chunk [k][col=bcq*16+kx]
    int t = threadIdx.x;
    int lane = t & 31, warp = t >> 5;
    int gid = lane >> 2, tig = lane & 3;
    int ks4 = blockIdx.x & 3;
    int bc0 = (blockIdx.x >> 2) * 2;
    float d[4][4] = {};
    for (int ci = 0; ci < 2; ci++) {
        int ch = ks4 * 2 + ci;
        int h0 = ch * 32, k0 = ch * 64;
        __syncthreads();
        for (int j = t; j < 1024; j += 128) {
            int row = j >> 4, q = j & 15;
            float4 h4 = *(const float4*)(g_Thi + (size_t)row * 512 + k0 + q * 4);
            th[row][q * 4 + 0] = h4.x; th[row][q * 4 + 1] = h4.y;
            th[row][q * 4 + 2] = h4.z; th[row][q * 4 + 3] = h4.w;
            float4 l4 = *(const float4*)(g_Tlo + (size_t)row * 512 + k0 + q * 4);
            tl[row][q * 4 + 0] = l4.x; tl[row][q * 4 + 1] = l4.y;
            tl[row][q * 4 + 2] = l4.z; tl[row][q * 4 + 3] = l4.w;
        }
        for (int j = t; j < 512; j += 128) {
            int bcq = j >> 8, rem = j & 255, hh = rem >> 3, q = rem & 7;
            float4 v4 = *(const float4*)(g_a + (size_t)((bc0 + bcq) * 256 + h0 + hh) * 32 + q * 4);
            int n0 = bcq * 16 + q * 2;
            as[2 * hh + 0][n0] = v4.x;     as[2 * hh + 1][n0] = v4.y;
            as[2 * hh + 0][n0 + 1] = v4.z; as[2 * hh + 1][n0 + 1] = v4.w;
        }
        __syncthreads();
        #pragma unroll
        for (int ks = 0; ks < 8; ks++) {
            int kk = ks * 8;
            int m0 = warp * 16 + gid;
            unsigned ah[4], al_[4];
            ah[0] = __float_as_uint(th[m0][kk + tig]);
            ah[1] = __float_as_uint(th[m0 + 8][kk + tig]);
            ah[2] = __float_as_uint(th[m0][kk + tig + 4]);
            ah[3] = __float_as_uint(th[m0 + 8][kk + tig + 4]);
            al_[0] = __float_as_uint(tl[m0][kk + tig]);
            al_[1] = __float_as_uint(tl[m0 + 8][kk + tig]);
            al_[2] = __float_as_uint(tl[m0][kk + tig + 4]);
            al_[3] = __float_as_uint(tl[m0 + 8][kk + tig + 4]);
            #pragma unroll
            for (int nt = 0; nt < 4; nt++) {
                int n = nt * 8 + gid;
                float b0 = as[kk + tig][n];
                float b1 = as[kk + tig + 4][n];
                unsigned bh0 = f2tf32(b0);
                unsigned bh1 = f2tf32(b1);
                unsigned bl0 = f2tf32(b0 - __uint_as_float(bh0));
                unsigned bl1 = f2tf32(b1 - __uint_as_float(bh1));
                MMA_TF32(d[nt], ah, bh0, bh1);
                MMA_TF32(d[nt], al_, bh0, bh1);
                MMA_TF32(d[nt], ah, bl0, bl1);
            }
        }
    }
    float* vout = g_vftp + (size_t)ks4 * PP;
    #pragma unroll
    for (int nt = 0; nt < 4; nt++) {
        #pragma unroll
        for (int e = 0; e < 4; e++) {
            int r = warp * 16 + gid + (e >= 2 ? 8 : 0);
            int c = nt * 8 + 2 * tig + (e & 1);
            int m = r >> 1, ri = r & 1;
            int bcq = c >> 4, kx = c & 15;
            vout[(bc0 + bcq) * 1024 + m * 32 + kx * 2 + ri] = d[nt][e];
        }
    }
}

// ---------------- per-mode 16x16 complex channel mixing (sums 4 partials)
__global__ void k_mix(const float* __restrict__ w1r, const float* __restrict__ w1i,
                      const float* __restrict__ w2r, const float* __restrict__ w2i,
                      int l) {
    int tid = blockIdx.x * blockDim.x + threadIdx.x;   // 131072
    int kx = tid & 15;
    int m = (tid >> 4) & 31;
    int o = (tid >> 9) & 15;
    int b = tid >> 13;
    int mm = m & 15;
    const float* wr = (m < 16) ? w1r : w2r;
    const float* wi = (m < 16) ? w1i : w2i;
    float accr = 0.f, acci = 0.f;
    #pragma unroll
    for (int i = 0; i < 16; i++) {
        int vidx = (b * 16 + i) * 1024 + m * 32 + kx * 2;
        float2 p0 = *(const float2*)(g_vftp + vidx);
        float2 p1 = *(const float2*)(g_vftp + PP + vidx);
        float2 p2 = *(const float2*)(g_vftp + 2 * PP + vidx);
        float2 p3 = *(const float2*)(g_vftp + 3 * PP + vidx);
        float vr = (p0.x + p1.x) + (p2.x + p3.x);
        float vv = (p0.y + p1.y) + (p2.y + p3.y);
        int widx = (((l * 16 + i) * 16 + o) * 256) + mm * 16 + kx;
        float wrv = wr[widx], wiv = wi[widx];
        accr += vr * wrv - vv * wiv;
        acci += vr * wiv + vv * wrv;
    }
    int outi = (b * 16 + o) * 1024 + m * 32 + kx * 2;
    g_mix[outi + 0] = accr;
    g_mix[outi + 1] = acci;
}

// ---------------- h-synthesis GEMM per bc: C[512,16] = E3[512,64] x M ----
__global__ void __launch_bounds__(256) k_hsynth() {
    __shared__ float mixT[16][68];    // [kx][2m+p]
    int t = threadIdx.x;
    int bc = blockIdx.x;
    {
        float4 v4 = *(const float4*)(g_mix + (size_t)bc * 1024 + t * 4);
        int i4 = t * 4;
        #pragma unroll
        for (int e = 0; e < 4; e++) {
            int idx = i4 + e;
            int m = idx >> 5, rem = idx & 31, kx = rem >> 1, p = rem & 1;
            float val = (e == 0) ? v4.x : (e == 1) ? v4.y : (e == 2) ? v4.z : v4.w;
            mixT[kx][2 * m + p] = val;
        }
    }
    __syncthreads();
    int rg = t >> 3, cg = t & 7;
    float acc[16][2] = {};
    for (int ks = 0; ks < 64; ks += 4) {
        float4 bf0 = *(const float4*)&mixT[cg * 2 + 0][ks];
        float4 bf1 = *(const float4*)&mixT[cg * 2 + 1][ks];
        #pragma unroll
        for (int i = 0; i < 16; i++) {
            float4 af = *(const float4*)(g_E3 + (size_t)(32 * i + rg) * 64 + ks);
            acc[i][0] += af.x * bf0.x + af.y * bf0.y + af.z * bf0.z + af.w * bf0.w;
            acc[i][1] += af.x * bf1.x + af.y * bf1.y + af.z * bf1.z + af.w * bf1.w;
        }
    }
    #pragma unroll
    for (int i = 0; i < 16; i++) {
        int r = 32 * i + rg, h = r >> 1, ro = r & 1;
        #pragma unroll
        for (int jj = 0; jj < 2; jj++) {
            int kx = cg * 2 + jj;
            float sc = (kx == 0) ? (1.0f / 65536.0f) : (2.0f / 65536.0f);
            g_gs[(size_t)(bc * 256 + h) * 32 + kx * 2 + ro] = acc[i][jj] * sc;
        }
    }
}

// ---------------- fused w-synth + skip (+ gelu | + proj1+gelu+pool) ------
__global__ void __launch_bounds__(256) k_wsynth(const float* __restrict__ skw,
                         const float* __restrict__ skb,
                         const float* __restrict__ pw1,
                         const float* __restrict__ pb1,
                         const float* __restrict__ x,
                         const float* __restrict__ lw,
                         const float* __restrict__ lb,
                         int l, int mode, int first, int flip) {
    __shared__ float vs[16][260];
    __shared__ float ms[16][52];      // [o][0:16 skw | 16:32 gr | 32:48 -gi]
    __shared__ float sb[16];
    __shared__ float outs[16][264];   // staged OUT for fused proj (mode 0)
    const float* __restrict__ vin = flip ? g_v1 : g_v0;
    float* __restrict__ vout = flip ? g_v0 : g_v1;
    int t = threadIdx.x;
    int lane = t & 31, warp = t >> 5;
    int b = blockIdx.x >> 8, h = blockIdx.x & 255;
    if (first) {
        const float* xrow = x + ((size_t)b * 256 + h) * 256;
        for (int j = t; j < 1024; j += 256) {
            int c = j >> 6, q = j & 63;
            float4 v4 = *(const float4*)(xrow + q * 4);
            float s = lw[c], o = lb[c];
            vs[c][q * 4 + 0] = s * v4.x + o; vs[c][q * 4 + 1] = s * v4.y + o;
            vs[c][q * 4 + 2] = s * v4.z + o; vs[c][q * 4 + 3] = s * v4.w + o;
        }
    } else {
        for (int j = t; j < 1024; j += 256) {
            int c = j >> 6, q = j & 63;
            float4 v4 = *(const float4*)(vin + ((size_t)(b * 16 + c) * 256 + h) * 256 + q * 4);
            vs[c][q * 4 + 0] = v4.x; vs[c][q * 4 + 1] = v4.y;
            vs[c][q * 4 + 2] = v4.z; vs[c][q * 4 + 3] = v4.w;
        }
    }
    {
        int c = t >> 4, k = t & 15;
        ms[c][k] = skw[l * 256 + c * 16 + k];
        int base = ((size_t)(b * 16 + c) * 256 + h) * 32 + k * 2;
        ms[c][16 + k] = g_gs[base];
        ms[c][32 + k] = -g_gs[base + 1];
        if (t < 16) sb[t] = skb[l * 16 + t];
    }
    __syncthreads();
    int gid = lane >> 2, tig = lane & 3;
    unsigned a[6][4];
    #pragma unroll
    for (int ks = 0; ks < 6; ks++) {
        int c0 = ks * 8 + tig;
        a[ks][0] = f2tf32(ms[gid][c0]);
        a[ks][1] = f2tf32(ms[gid + 8][c0]);
        a[ks][2] = f2tf32(ms[gid][c0 + 4]);
        a[ks][3] = f2tf32(ms[gid + 8][c0 + 4]);
    }
    float bias0 = sb[gid], bias1 = sb[gid + 8];
    float* out0 = vout + ((size_t)(b * 16 + gid) * 256 + h) * 256;
    float* out1 = vout + ((size_t)(b * 16 + gid + 8) * 256 + h) * 256;
    #pragma unroll
    for (int nt = 0; nt < 4; nt++) {
        int n = warp * 32 + nt * 8 + gid;
        unsigned bf[6][2];
        bf[0][0] = f2tf32(vs[tig][n]);        bf[0][1] = f2tf32(vs[tig + 4][n]);
        bf[1][0] = f2tf32(vs[8 + tig][n]);    bf[1][1] = f2tf32(vs[12 + tig][n]);
        bf[2][0] = f2tf32(g_xc[tig * 256 + n]);
        bf[2][1] = f2tf32(g_xc[(tig + 4) * 256 + n]);
        bf[3][0] = f2tf32(g_xc[(8 + tig) * 256 + n]);
        bf[3][1] = f2tf32(g_xc[(12 + tig) * 256 + n]);
        bf[4][0] = f2tf32(g_xs[tig * 256 + n]);
        bf[4][1] = f2tf32(g_xs[(tig + 4) * 256 + n]);
        bf[5][0] = f2tf32(g_xs[(8 + tig) * 256 + n]);
        bf[5][1] = f2tf32(g_xs[(12 + tig) * 256 + n]);
        float d0 = 0.f, d1 = 0.f, d2 = 0.f, d3 = 0.f;
        #pragma unroll
        for (int ks = 0; ks < 6; ks++) {
            asm volatile(
                "mma.sync.aligned.m16n8k8.row.col.f32.tf32.tf32.f32 "
                "{%0,%1,%2,%3}, {%4,%5,%6,%7}, {%8,%9}, {%0,%1,%2,%3};\n"
                : "+f"(d0), "+f"(d1), "+f"(d2), "+f"(d3)
                : "r"(a[ks][0]), "r"(a[ks][1]), "r"(a[ks][2]), "r"(a[ks][3]),
                  "r"(bf[ks][0]), "r"(bf[ks][1]));
        }
        d0 += bias0; d1 += bias0; d2 += bias1; d3 += bias1;
        int w = warp * 32 + nt * 8 + 2 * tig;
        if (mode) {
            d0 = gelu_t(d0); d1 = gelu_t(d1);
            d2 = gelu_t(d2); d3 = gelu_t(d3);
            *(float2*)(out0 + w) = make_float2(d0, d1);
            *(float2*)(out1 + w) = make_float2(d2, d3);
        } else {
            outs[gid][w] = d0;     outs[gid][w + 1] = d1;
            outs[gid + 8][w] = d2; outs[gid + 8][w + 1] = d3;
        }
    }
    if (mode) return;
    // ---- fused proj1 + gelu + pool (mode 0) ----
    __syncthreads();
    int m_base = warp * 16;
    unsigned pa[2][4];
    float pb[2];
    {
        int r_lo = m_base + gid;
        pb[0] = pb1[r_lo];
        pb[1] = pb1[r_lo + 8];
        #pragma unroll
        for (int ks = 0; ks < 2; ks++) {
            int c_lo = ks * 8 + tig;
            pa[ks][0] = f2tf32(pw1[r_lo * 16 + c_lo]);
            pa[ks][1] = f2tf32(pw1[(r_lo + 8) * 16 + c_lo]);
            pa[ks][2] = f2tf32(pw1[r_lo * 16 + c_lo + 4]);
            pa[ks][3] = f2tf32(pw1[(r_lo + 8) * 16 + c_lo + 4]);
        }
    }
    float s0 = 0.f, s1 = 0.f;
    #pragma unroll
    for (int nt = 0; nt < 32; nt++) {
        int n = nt * 8 + gid;
        unsigned bfr[2][2];
        bfr[0][0] = f2tf32(outs[tig][n]);
        bfr[0][1] = f2tf32(outs[tig + 4][n]);
        bfr[1][0] = f2tf32(outs[8 + tig][n]);
        bfr[1][1] = f2tf32(outs[12 + tig][n]);
        float d0 = 0.f, d1 = 0.f, d2 = 0.f, d3 = 0.f;
        #pragma unroll
        for (int ks = 0; ks < 2; ks++) {
            asm volatile(
                "mma.sync.aligned.m16n8k8.row.col.f32.tf32.tf32.f32 "
                "{%0,%1,%2,%3}, {%4,%5,%6,%7}, {%8,%9}, {%0,%1,%2,%3};\n"
                : "+f"(d0), "+f"(d1), "+f"(d2), "+f"(d3)
                : "r"(pa[ks][0]), "r"(pa[ks][1]), "r"(pa[ks][2]), "r"(pa[ks][3]),
                  "r"(bfr[ks][0]), "r"(bfr[ks][1]));
        }
        s0 += gelu_t(d0 + pb[0]) + gelu_t(d1 + pb[0]);
        s1 += gelu_t(d2 + pb[1]) + gelu_t(d3 + pb[1]);
    }
    s0 += __shfl_xor_sync(0xFFFFFFFFu, s0, 1);
    s0 += __shfl_xor_sync(0xFFFFFFFFu, s0, 2);
    s1 += __shfl_xor_sync(0xFFFFFFFFu, s1, 1);
    s1 += __shfl_xor_sync(0xFFFFFFFFu, s1, 2);
    if (tig == 0) {
        float* dst = g_pool + (size_t)(b * 256 + h) * 128;
        dst[m_base + gid] = s0;
        dst[m_base + gid + 8] = s1;
    }
}

// ---------------- final reduce + proj2 on pooled vector + head -----------
__global__ void k_head(const float* __restrict__ w2, const float* __restrict__ b2,
                       const float* __restrict__ hw_, const float* __restrict__ hb,
                       float* __restrict__ out) {
    __shared__ float pq[128];
    __shared__ float f[64];
    int b = blockIdx.x, t = threadIdx.x;
    float s = 0.f;
    for (int k = 0; k < 256; k++)
        s += g_pool[((size_t)(b * 256 + k)) * 128 + t];
    pq[t] = s * (1.0f / 65536.0f);
    __syncthreads();
    if (t < 64) {
        float a = b2[t];
        #pragma unroll 8
        for (int i = 0; i < 128; i++) a += w2[t * 128 + i] * pq[i];
        f[t] = a;
    }
    __syncthreads();
    if (t < 2) {
        float a = hb[t];
        #pragma unroll
        for (int o = 0; o < 64; o++) a += hw_[t * 64 + o] * f[o];
        float e = __expf(2.0f * a);
        out[b * 2 + t] = 1.0f - 2.0f / (e + 1.0f);
    }
}

extern "C" void kernel_launch(void* const* d_in, const int* in_sizes, int n_in,
                              void* d_out, int out_size) {
    const float* x    = (const float*)d_in[0];
    const float* lw   = (const float*)d_in[1];
    const float* lb   = (const float*)d_in[2];
    const float* w1r  = (const float*)d_in[3];
    const float* w1i  = (const float*)d_in[4];
    const float* w2r  = (const float*)d_in[5];
    const float* w2i  = (const float*)d_in[6];
    const float* skw  = (const float*)d_in[7];
    const float* skb  = (const float*)d_in[8];
    const float* pw1  = (const float*)d_in[9];
    const float* pb1  = (const float*)d_in[10];
    const float* pw2  = (const float*)d_in[11];
    const float* pb2  = (const float*)d_in[12];
    const float* hw_  = (const float*)d_in[13];
    const float* hb   = (const float*)d_in[14];
    float* out = (float*)d_out;

    k_tw<<<448, 256>>>();
    for (int l = 0; l < Ln; l++) {
        int flip = l & 1;
        if (l == 0) {
            k_xdft0 <<<64, 128>>>(x);
            k_expand<<<2048, 256>>>(lw, lb);
        } else {
            k_xdft  <<<1024, 128>>>(flip);
        }
        k_ydft  <<<512, 128>>>();
        k_mix   <<<512, 256>>>(w1r, w1i, w2r, w2i, l);
        k_hsynth<<<256, 256>>>();
        k_wsynth<<<4096, 256>>>(skw, skb, pw1, pb1, x, lw, lb, l,
                                (l < Ln - 1) ? 1 : 0, (l == 0) ? 1 : 0, flip);
    }
    k_head<<<Bn, 128>>>(pw2, pb2, hw_, hb, out);
}